// round 6
// baseline (speedup 1.0000x reference)
#include <cuda_runtime.h>

#define BB 64
#define II 512
#define HH 1024
#define NCHUNK 64              // h-dimension split for rec partials
#define HCHUNK (HH / NCHUNK)   // 16
#define BTILE 4                // batches per block in rec kernel
#define BGROUPS (BB / BTILE)   // 16
#define CROWS 8                // (b,h) rows per block in hebb update
#define CLIPV 2.0f
#define LN_EPS 1e-5f

// Scratch (no allocations allowed -> __device__ globals)
__device__ float g_rec_part[NCHUNK][BB][HH];   // 16 MB partial sums
__device__ float g_gemm[BB][HH];               // x @ fc_w^T  +  h_pre @ weight
__device__ float g_etah[BB][HH];               // eta * h_post

__device__ __forceinline__ float4 ldcs4(const float4* p)
{
    float4 v;
    asm volatile("ld.global.cs.v4.f32 {%0,%1,%2,%3}, [%4];"
                 : "=f"(v.x), "=f"(v.y), "=f"(v.z), "=f"(v.w) : "l"(p));
    return v;
}

__device__ __forceinline__ void stcs4(float4* p, float4 v)
{
    asm volatile("st.global.cs.v4.f32 [%0], {%1,%2,%3,%4};"
                 :: "l"(p), "f"(v.x), "f"(v.y), "f"(v.z), "f"(v.w));
}

// ---------------------------------------------------------------------------
// Kernel A: rec hebb partials (weight term removed -> rec_w_kernel).
// part[chunk][b][k] = sum_{h in chunk} h_pre[b,h] * alpha[h,k] * hebb[b,h,k]
// Grid = 64 x 16 = 1024 blocks, 256 threads (one float4 k-lane each).
// 5 loads/iter (1 alpha L2 + 4 hebb DRAM streams), unroll 2 -> 10/batch.
// __launch_bounds__(256,4) caps regs at 64 -> 4 blocks/SM = 32 warps.
// ---------------------------------------------------------------------------
__global__ __launch_bounds__(256, 4) void rec_partial_kernel(
    const float* __restrict__ h_pre, const float* __restrict__ hebb,
    const float* __restrict__ alpha)
{
    const int chunk = blockIdx.x;        // 0..NCHUNK-1
    const int bg    = blockIdx.y;        // 0..BGROUPS-1
    const int tid   = threadIdx.x;       // 0..255 -> float4 lane over k
    const int b0    = bg * BTILE;
    const int h0    = chunk * HCHUNK;

    __shared__ float hp[BTILE][HCHUNK];
    if (tid < BTILE * HCHUNK) {
        int j  = tid >> 4;               // 0..3
        int hh = tid & 15;               // 0..15
        hp[j][hh] = h_pre[(b0 + j) * HH + h0 + hh];
    }
    __syncthreads();

    const float4* a4 = reinterpret_cast<const float4*>(alpha);
    const float4* e4 = reinterpret_cast<const float4*>(hebb);

    float4 acc[BTILE];
#pragma unroll
    for (int j = 0; j < BTILE; ++j) acc[j] = make_float4(0.f, 0.f, 0.f, 0.f);

    const float4* pj[BTILE];
#pragma unroll
    for (int j = 0; j < BTILE; ++j)
        pj[j] = e4 + ((b0 + j) * HH + h0) * (HH / 4) + tid;

#pragma unroll 2
    for (int hi = 0; hi < HCHUNK; ++hi) {
        const int h = h0 + hi;
        const float4 a = a4[h * (HH / 4) + tid];
        float4 e[BTILE];
#pragma unroll
        for (int j = 0; j < BTILE; ++j)
            e[j] = ldcs4(pj[j] + hi * (HH / 4));
#pragma unroll
        for (int j = 0; j < BTILE; ++j) {
            const float s = hp[j][hi];
            acc[j].x = fmaf(s * a.x, e[j].x, acc[j].x);
            acc[j].y = fmaf(s * a.y, e[j].y, acc[j].y);
            acc[j].z = fmaf(s * a.z, e[j].z, acc[j].z);
            acc[j].w = fmaf(s * a.w, e[j].w, acc[j].w);
        }
    }

#pragma unroll
    for (int j = 0; j < BTILE; ++j) {
        float4* dst = reinterpret_cast<float4*>(&g_rec_part[chunk][b0 + j][0]);
        dst[tid] = acc[j];
    }
}

// ---------------------------------------------------------------------------
// Kernel B1: g_gemm[b,k] = sum_i x[b,i] * fc_w[k,i]   (64x1024x512, tiny)
// ---------------------------------------------------------------------------
__global__ __launch_bounds__(256) void gemm_kernel(
    const float* __restrict__ x, const float* __restrict__ fc_w)
{
    __shared__ float xs[64][33];
    __shared__ float ws[64][33];
    const int k0  = blockIdx.x * 64;
    const int tid = threadIdx.x;
    const int tx  = tid & 15;   // k sub-tile
    const int ty  = tid >> 4;   // b sub-tile

    float acc[4][4];
#pragma unroll
    for (int i = 0; i < 4; ++i)
#pragma unroll
        for (int j = 0; j < 4; ++j) acc[i][j] = 0.f;

    for (int i0 = 0; i0 < II; i0 += 32) {
        __syncthreads();
#pragma unroll
        for (int r = 0; r < 8; ++r) {
            int idx = tid + r * 256;
            int row = idx >> 5;   // 0..63
            int col = idx & 31;   // 0..31
            xs[row][col] = x[row * II + i0 + col];
            ws[row][col] = fc_w[(k0 + row) * II + i0 + col];
        }
        __syncthreads();
#pragma unroll
        for (int ii = 0; ii < 32; ++ii) {
            float xv[4], wv[4];
#pragma unroll
            for (int q = 0; q < 4; ++q) { xv[q] = xs[ty * 4 + q][ii]; wv[q] = ws[tx * 4 + q][ii]; }
#pragma unroll
            for (int bi = 0; bi < 4; ++bi)
#pragma unroll
                for (int ki = 0; ki < 4; ++ki)
                    acc[bi][ki] = fmaf(xv[bi], wv[ki], acc[bi][ki]);
        }
    }

#pragma unroll
    for (int bi = 0; bi < 4; ++bi)
#pragma unroll
        for (int ki = 0; ki < 4; ++ki)
            g_gemm[ty * 4 + bi][k0 + tx * 4 + ki] = acc[bi][ki];
}

// ---------------------------------------------------------------------------
// Kernel B1b: g_gemm[b,k] += sum_h h_pre[b,h] * weight[h,k]  (64x1024x1024)
// Same tiling; weight accessed [h][k] (reduction along rows, coalesced in k).
// Must run AFTER gemm_kernel (accumulates).
// ---------------------------------------------------------------------------
__global__ __launch_bounds__(256) void rec_w_kernel(
    const float* __restrict__ h_pre, const float* __restrict__ weight)
{
    __shared__ float xs[64][33];   // h_pre tile: [b][h-chunk]
    __shared__ float ws[32][65];   // weight tile: [h-chunk][k-tile]
    const int k0  = blockIdx.x * 64;
    const int tid = threadIdx.x;
    const int tx  = tid & 15;   // k sub-tile
    const int ty  = tid >> 4;   // b sub-tile

    float acc[4][4];
#pragma unroll
    for (int i = 0; i < 4; ++i)
#pragma unroll
        for (int j = 0; j < 4; ++j) acc[i][j] = 0.f;

    for (int i0 = 0; i0 < HH; i0 += 32) {
        __syncthreads();
#pragma unroll
        for (int r = 0; r < 8; ++r) {
            int idx = tid + r * 256;
            int row = idx >> 5;   // 0..63
            int col = idx & 31;   // 0..31
            xs[row][col] = h_pre[row * HH + i0 + col];
        }
#pragma unroll
        for (int r = 0; r < 8; ++r) {
            int idx = tid + r * 256;
            int row = idx >> 6;   // 0..31 (h within chunk)
            int col = idx & 63;   // 0..63 (k within tile)
            ws[row][col] = weight[(i0 + row) * HH + k0 + col];
        }
        __syncthreads();
#pragma unroll
        for (int ii = 0; ii < 32; ++ii) {
            float xv[4], wv[4];
#pragma unroll
            for (int q = 0; q < 4; ++q) { xv[q] = xs[ty * 4 + q][ii]; wv[q] = ws[ii][tx * 4 + q]; }
#pragma unroll
            for (int bi = 0; bi < 4; ++bi)
#pragma unroll
                for (int ki = 0; ki < 4; ++ki)
                    acc[bi][ki] = fmaf(xv[bi], wv[ki], acc[bi][ki]);
        }
    }

#pragma unroll
    for (int bi = 0; bi < 4; ++bi)
#pragma unroll
        for (int ki = 0; ki < 4; ++ki)
            g_gemm[ty * 4 + bi][k0 + tx * 4 + ki] += acc[bi][ki];
}

// ---------------------------------------------------------------------------
// Kernel B2: per-batch fused epilogue.
// ---------------------------------------------------------------------------
__device__ __forceinline__ float block_reduce_sum(float v, float* sred, int tid)
{
#pragma unroll
    for (int o = 16; o > 0; o >>= 1) v += __shfl_down_sync(0xffffffffu, v, o);
    if ((tid & 31) == 0) sred[tid >> 5] = v;
    __syncthreads();
    if (tid < 8) {
        float x = sred[tid];
#pragma unroll
        for (int o = 4; o > 0; o >>= 1) x += __shfl_down_sync(0xffu, x, o);
        if (tid == 0) sred[0] = x;
    }
    __syncthreads();
    float r = sred[0];
    __syncthreads();   // protect sred for next reduction
    return r;
}

__global__ __launch_bounds__(256) void ln_mod_kernel(
    const float* __restrict__ fc_b,
    const float* __restrict__ ln_g,  const float* __restrict__ ln_b,
    const float* __restrict__ mod_w, const float* __restrict__ mod_b,
    const float* __restrict__ modf_w, const float* __restrict__ modf_b,
    float* __restrict__ out_hpost, float* __restrict__ out_m)
{
    const int b   = blockIdx.x;
    const int tid = threadIdx.x;
    __shared__ float sred[8];
    __shared__ float sm;

    // pre = gemm(+rec_w) + fc_b + sum of NCHUNK rec partials
    float4 v  = reinterpret_cast<const float4*>(&g_gemm[b][0])[tid];
    float4 fb = reinterpret_cast<const float4*>(fc_b)[tid];
    v.x += fb.x; v.y += fb.y; v.z += fb.z; v.w += fb.w;
#pragma unroll 8
    for (int c = 0; c < NCHUNK; ++c) {
        float4 p = reinterpret_cast<const float4*>(&g_rec_part[c][b][0])[tid];
        v.x += p.x; v.y += p.y; v.z += p.z; v.w += p.w;
    }

    float s  = v.x + v.y + v.z + v.w;
    float s2 = v.x * v.x + v.y * v.y + v.z * v.z + v.w * v.w;
    s  = block_reduce_sum(s,  sred, tid);
    s2 = block_reduce_sum(s2, sred, tid);
    const float mu   = s / (float)HH;
    const float var  = s2 / (float)HH - mu * mu;
    const float rstd = rsqrtf(var + LN_EPS);

    float4 g  = reinterpret_cast<const float4*>(ln_g)[tid];
    float4 be = reinterpret_cast<const float4*>(ln_b)[tid];
    float4 hp;
    hp.x = tanhf((v.x - mu) * rstd * g.x + be.x);
    hp.y = tanhf((v.y - mu) * rstd * g.y + be.y);
    hp.z = tanhf((v.z - mu) * rstd * g.z + be.z);
    hp.w = tanhf((v.w - mu) * rstd * g.w + be.w);
    reinterpret_cast<float4*>(out_hpost + b * HH)[tid] = hp;

    // m = tanh(dot(h_post, mod_w) + mod_b)
    float4 mw = reinterpret_cast<const float4*>(mod_w)[tid];
    float d = hp.x * mw.x + hp.y * mw.y + hp.z * mw.z + hp.w * mw.w;
    d = block_reduce_sum(d, sred, tid);
    if (tid == 0) {
        float m = tanhf(d + mod_b[0]);
        out_m[b] = m;
        sm = m;
    }
    __syncthreads();
    const float m = sm;

    // etah[b,k] = (m*modf_w[k] + modf_b[k]) * h_post[b,k]
    float4 fw  = reinterpret_cast<const float4*>(modf_w)[tid];
    float4 fbb = reinterpret_cast<const float4*>(modf_b)[tid];
    float4 t;
    t.x = fmaf(m, fw.x, fbb.x) * hp.x;
    t.y = fmaf(m, fw.y, fbb.y) * hp.y;
    t.z = fmaf(m, fw.z, fbb.z) * hp.z;
    t.w = fmaf(m, fw.w, fbb.w) * hp.w;
    reinterpret_cast<float4*>(&g_etah[b][0])[tid] = t;
}

// ---------------------------------------------------------------------------
// Kernel C: hebb_new[b,h,k] = clip(hebb[b,h,k] + h_pre[b,h]*etah[b,k])
// R3/R5-measured at ~76% of HBM spec (practical ceiling); unchanged.
// ---------------------------------------------------------------------------
__global__ __launch_bounds__(256) void hebb_update_kernel(
    const float* __restrict__ h_pre, const float* __restrict__ hebb,
    float* __restrict__ out_hebb)
{
    const int row0 = blockIdx.x * CROWS;
    const int tid  = threadIdx.x;
#pragma unroll
    for (int r = 0; r < CROWS; ++r) {
        const int bh = row0 + r;
        const int b  = bh >> 10;
        const float hpv = __ldg(&h_pre[bh]);   // h_pre[b*H + h] == h_pre[bh]
        const float4 e = ldcs4(reinterpret_cast<const float4*>(hebb) + bh * (HH / 4) + tid);
        const float4 t = reinterpret_cast<const float4*>(&g_etah[b][0])[tid];
        float4 o;
        o.x = fminf(fmaxf(fmaf(hpv, t.x, e.x), -CLIPV), CLIPV);
        o.y = fminf(fmaxf(fmaf(hpv, t.y, e.y), -CLIPV), CLIPV);
        o.z = fminf(fmaxf(fmaf(hpv, t.z, e.z), -CLIPV), CLIPV);
        o.w = fminf(fmaxf(fmaf(hpv, t.w, e.w), -CLIPV), CLIPV);
        stcs4(reinterpret_cast<float4*>(out_hebb) + bh * (HH / 4) + tid, o);
    }
}

// ---------------------------------------------------------------------------
// Launch. Inputs in metadata order:
// 0 x, 1 h_pre, 2 hebb, 3 fc_w, 4 fc_b, 5 weight, 6 alpha,
// 7 ln_g, 8 ln_b, 9 mod_w, 10 mod_b, 11 modf_w, 12 modf_b
// Output: h_post [64*1024] | m [64] | hebb_new [64*1024*1024], fp32.
// ---------------------------------------------------------------------------
extern "C" void kernel_launch(void* const* d_in, const int* in_sizes, int n_in,
                              void* d_out, int out_size)
{
    const float* x      = (const float*)d_in[0];
    const float* h_pre  = (const float*)d_in[1];
    const float* hebb   = (const float*)d_in[2];
    const float* fc_w   = (const float*)d_in[3];
    const float* fc_b   = (const float*)d_in[4];
    const float* weight = (const float*)d_in[5];
    const float* alpha  = (const float*)d_in[6];
    const float* ln_g   = (const float*)d_in[7];
    const float* ln_b   = (const float*)d_in[8];
    const float* mod_w  = (const float*)d_in[9];
    const float* mod_b  = (const float*)d_in[10];
    const float* modf_w = (const float*)d_in[11];
    const float* modf_b = (const float*)d_in[12];

    float* out       = (float*)d_out;
    float* out_hpost = out;                 // 64*1024
    float* out_m     = out + BB * HH;       // 64
    float* out_hebb  = out + BB * HH + BB;  // 64*1024*1024

    gemm_kernel<<<HH / 64, 256>>>(x, fc_w);
    rec_w_kernel<<<HH / 64, 256>>>(h_pre, weight);
    rec_partial_kernel<<<dim3(NCHUNK, BGROUPS), 256>>>(h_pre, hebb, alpha);
    ln_mod_kernel<<<BB, 256>>>(fc_b, ln_g, ln_b, mod_w, mod_b, modf_w, modf_b,
                               out_hpost, out_m);
    hebb_update_kernel<<<(BB * HH) / CROWS, 256>>>(h_pre, hebb, out_hebb);
}

// round 7
// speedup vs baseline: 1.3070x; 1.3070x over previous
#include <cuda_runtime.h>

#define BB 64
#define II 512
#define HH 1024
#define NCHUNK 32              // h-dimension split for rec partials
#define HCHUNK (HH / NCHUNK)   // 32
#define BTILE 4                // batches per block in rec kernel
#define BGROUPS (BB / BTILE)   // 16
#define CROWS 8                // (b,h) rows per block in hebb update
#define CLIPV 2.0f
#define LN_EPS 1e-5f

// Scratch (no allocations allowed -> __device__ globals)
__device__ float g_rec_part[NCHUNK][BB][HH];   // 8 MB partial sums (.wb -> L2)
__device__ float g_gemm[BB][HH];               // x @ fc_w^T
__device__ float g_pre[BB][HH];                // gemm + fc_b + sum(partials)
__device__ float g_etah[BB][HH];               // eta * h_post

__device__ __forceinline__ float4 ldcs4(const float4* p)
{
    float4 v;
    asm volatile("ld.global.cs.v4.f32 {%0,%1,%2,%3}, [%4];"
                 : "=f"(v.x), "=f"(v.y), "=f"(v.z), "=f"(v.w) : "l"(p));
    return v;
}

__device__ __forceinline__ void stcs4(float4* p, float4 v)
{
    asm volatile("st.global.cs.v4.f32 [%0], {%1,%2,%3,%4};"
                 :: "l"(p), "f"(v.x), "f"(v.y), "f"(v.z), "f"(v.w));
}

// ---------------------------------------------------------------------------
// Kernel A: rec partials (R5-measured config, 188us total run).
// part[chunk][b][k] = sum_{h in chunk} h_pre[b,h]*(weight[h,k]+alpha[h,k]*hebb[b,h,k])
// Grid = 32 x 16 = 512 blocks, 256 threads (one float4 k-lane each).
// weight/alpha L2-amortized over 4 batches; 4 hebb DRAM streams/thread,
// unroll 2 -> ~12 independent loads per issue batch.
// ---------------------------------------------------------------------------
__global__ __launch_bounds__(256) void rec_partial_kernel(
    const float* __restrict__ h_pre, const float* __restrict__ hebb,
    const float* __restrict__ weight, const float* __restrict__ alpha)
{
    const int chunk = blockIdx.x;        // 0..NCHUNK-1
    const int bg    = blockIdx.y;        // 0..BGROUPS-1
    const int tid   = threadIdx.x;       // 0..255 -> float4 lane over k
    const int b0    = bg * BTILE;
    const int h0    = chunk * HCHUNK;

    __shared__ float hp[BTILE][HCHUNK];
    if (tid < BTILE * HCHUNK) {
        int j  = tid >> 5;               // 0..3
        int hh = tid & 31;               // 0..31
        hp[j][hh] = h_pre[(b0 + j) * HH + h0 + hh];
    }
    __syncthreads();

    const float4* w4 = reinterpret_cast<const float4*>(weight);
    const float4* a4 = reinterpret_cast<const float4*>(alpha);
    const float4* e4 = reinterpret_cast<const float4*>(hebb);

    float4 acc[BTILE];
#pragma unroll
    for (int j = 0; j < BTILE; ++j) acc[j] = make_float4(0.f, 0.f, 0.f, 0.f);

    const float4* pj[BTILE];
#pragma unroll
    for (int j = 0; j < BTILE; ++j)
        pj[j] = e4 + ((b0 + j) * HH + h0) * (HH / 4) + tid;

#pragma unroll 2
    for (int hi = 0; hi < HCHUNK; ++hi) {
        const int h = h0 + hi;
        const float4 w = w4[h * (HH / 4) + tid];
        const float4 a = a4[h * (HH / 4) + tid];
        float4 e[BTILE];
#pragma unroll
        for (int j = 0; j < BTILE; ++j)
            e[j] = ldcs4(pj[j] + hi * (HH / 4));
#pragma unroll
        for (int j = 0; j < BTILE; ++j) {
            const float s = hp[j][hi];
            acc[j].x += s * fmaf(a.x, e[j].x, w.x);
            acc[j].y += s * fmaf(a.y, e[j].y, w.y);
            acc[j].z += s * fmaf(a.z, e[j].z, w.z);
            acc[j].w += s * fmaf(a.w, e[j].w, w.w);
        }
    }

#pragma unroll
    for (int j = 0; j < BTILE; ++j) {
        float4* dst = reinterpret_cast<float4*>(&g_rec_part[chunk][b0 + j][0]);
        dst[tid] = acc[j];   // .wb: keep in L2 for presum
    }
}

// ---------------------------------------------------------------------------
// Kernel B1: g_gemm[b,k] = sum_i x[b,i] * fc_w[k,i]   (64x1024x512)
// 64 blocks (was 16 -> FMA-parallelism-starved, ~14us). Each block: 64 b x
// 16 k over full I. 256 threads = 16(tx:k) x 16(ty: 4-b groups), acc[4].
// ---------------------------------------------------------------------------
__global__ __launch_bounds__(256) void gemm_kernel(
    const float* __restrict__ x, const float* __restrict__ fc_w)
{
    __shared__ float xs[64][33];   // [b][i-chunk]
    __shared__ float ws[16][33];   // [k][i-chunk]
    const int k0  = blockIdx.x * 16;
    const int tid = threadIdx.x;
    const int tx  = tid & 15;   // k within tile
    const int ty  = tid >> 4;   // b group (4 rows)

    float acc[4] = {0.f, 0.f, 0.f, 0.f};

    for (int i0 = 0; i0 < II; i0 += 32) {
        __syncthreads();
#pragma unroll
        for (int r = 0; r < 8; ++r) {
            int idx = tid + r * 256;
            int row = idx >> 5;   // 0..63
            int col = idx & 31;   // 0..31
            xs[row][col] = x[row * II + i0 + col];
        }
        {
            int row = tid >> 5;   // 0..7 -> two passes cover 16 rows
            int col = tid & 31;
            ws[row][col]     = fc_w[(k0 + row) * II + i0 + col];
            ws[row + 8][col] = fc_w[(k0 + row + 8) * II + i0 + col];
        }
        __syncthreads();
#pragma unroll
        for (int ii = 0; ii < 32; ++ii) {
            const float wv = ws[tx][ii];
#pragma unroll
            for (int q = 0; q < 4; ++q)
                acc[q] = fmaf(xs[ty * 4 + q][ii], wv, acc[q]);
        }
    }

#pragma unroll
    for (int q = 0; q < 4; ++q)
        g_gemm[ty * 4 + q][k0 + tx] = acc[q];
}

// ---------------------------------------------------------------------------
// Kernel B1b: presum. g_pre[b,k] = g_gemm[b,k] + fc_b[k] + sum_c part[c][b][k]
// Grid (64 b, 8 k-slices of 128 floats) = 512 blocks, 256 threads:
// warp cg (0..7) sums chunks cg*4..cg*4+3 for its 32 float4 lanes; smem
// cross-warp reduce; warp 0 writes. Partials are L2-hot -> ~2us.
// ---------------------------------------------------------------------------
__global__ __launch_bounds__(256) void presum_kernel(const float* __restrict__ fc_b)
{
    const int b    = blockIdx.x;
    const int sl   = blockIdx.y;          // k-slice: 128 floats = 32 float4
    const int tid  = threadIdx.x;
    const int lane = tid & 31;            // float4 lane within slice
    const int cg   = tid >> 5;            // chunk group 0..7

    const int f4base = sl * 32 + lane;    // float4 index within row

    float4 s = make_float4(0.f, 0.f, 0.f, 0.f);
#pragma unroll
    for (int c = 0; c < 4; ++c) {
        const float4 p = reinterpret_cast<const float4*>(&g_rec_part[cg * 4 + c][b][0])[f4base];
        s.x += p.x; s.y += p.y; s.z += p.z; s.w += p.w;
    }

    __shared__ float4 red[8][32];
    red[cg][lane] = s;
    __syncthreads();

    if (cg == 0) {
        float4 v = red[0][lane];
#pragma unroll
        for (int g = 1; g < 8; ++g) {
            const float4 p = red[g][lane];
            v.x += p.x; v.y += p.y; v.z += p.z; v.w += p.w;
        }
        const float4 gm = reinterpret_cast<const float4*>(&g_gemm[b][0])[f4base];
        const float4 fb = reinterpret_cast<const float4*>(fc_b)[f4base];
        v.x += gm.x + fb.x; v.y += gm.y + fb.y;
        v.z += gm.z + fb.z; v.w += gm.w + fb.w;
        reinterpret_cast<float4*>(&g_pre[b][0])[f4base] = v;
    }
}

// ---------------------------------------------------------------------------
// Kernel B2: per-batch LN + tanh + m + etah (reads only g_pre, L2-hot).
// ---------------------------------------------------------------------------
__device__ __forceinline__ float block_reduce_sum(float v, float* sred, int tid)
{
#pragma unroll
    for (int o = 16; o > 0; o >>= 1) v += __shfl_down_sync(0xffffffffu, v, o);
    if ((tid & 31) == 0) sred[tid >> 5] = v;
    __syncthreads();
    if (tid < 8) {
        float x = sred[tid];
#pragma unroll
        for (int o = 4; o > 0; o >>= 1) x += __shfl_down_sync(0xffu, x, o);
        if (tid == 0) sred[0] = x;
    }
    __syncthreads();
    float r = sred[0];
    __syncthreads();   // protect sred for next reduction
    return r;
}

__global__ __launch_bounds__(256) void ln_mod_kernel(
    const float* __restrict__ ln_g,  const float* __restrict__ ln_b,
    const float* __restrict__ mod_w, const float* __restrict__ mod_b,
    const float* __restrict__ modf_w, const float* __restrict__ modf_b,
    float* __restrict__ out_hpost, float* __restrict__ out_m)
{
    const int b   = blockIdx.x;
    const int tid = threadIdx.x;
    __shared__ float sred[8];
    __shared__ float sm;

    float4 v = reinterpret_cast<const float4*>(&g_pre[b][0])[tid];

    float s  = v.x + v.y + v.z + v.w;
    float s2 = v.x * v.x + v.y * v.y + v.z * v.z + v.w * v.w;
    s  = block_reduce_sum(s,  sred, tid);
    s2 = block_reduce_sum(s2, sred, tid);
    const float mu   = s / (float)HH;
    const float var  = s2 / (float)HH - mu * mu;
    const float rstd = rsqrtf(var + LN_EPS);

    float4 g  = reinterpret_cast<const float4*>(ln_g)[tid];
    float4 be = reinterpret_cast<const float4*>(ln_b)[tid];
    float4 hp;
    hp.x = tanhf((v.x - mu) * rstd * g.x + be.x);
    hp.y = tanhf((v.y - mu) * rstd * g.y + be.y);
    hp.z = tanhf((v.z - mu) * rstd * g.z + be.z);
    hp.w = tanhf((v.w - mu) * rstd * g.w + be.w);
    reinterpret_cast<float4*>(out_hpost + b * HH)[tid] = hp;

    // m = tanh(dot(h_post, mod_w) + mod_b)
    float4 mw = reinterpret_cast<const float4*>(mod_w)[tid];
    float d = hp.x * mw.x + hp.y * mw.y + hp.z * mw.z + hp.w * mw.w;
    d = block_reduce_sum(d, sred, tid);
    if (tid == 0) {
        float m = tanhf(d + mod_b[0]);
        out_m[b] = m;
        sm = m;
    }
    __syncthreads();
    const float m = sm;

    // etah[b,k] = (m*modf_w[k] + modf_b[k]) * h_post[b,k]
    float4 fw  = reinterpret_cast<const float4*>(modf_w)[tid];
    float4 fbb = reinterpret_cast<const float4*>(modf_b)[tid];
    float4 t;
    t.x = fmaf(m, fw.x, fbb.x) * hp.x;
    t.y = fmaf(m, fw.y, fbb.y) * hp.y;
    t.z = fmaf(m, fw.z, fbb.z) * hp.z;
    t.w = fmaf(m, fw.w, fbb.w) * hp.w;
    reinterpret_cast<float4*>(&g_etah[b][0])[tid] = t;
}

// ---------------------------------------------------------------------------
// Kernel C: hebb_new[b,h,k] = clip(hebb[b,h,k] + h_pre[b,h]*etah[b,k])
// Measured at ~76% of HBM spec in R3/R5/R6 (practical ceiling); unchanged.
// ---------------------------------------------------------------------------
__global__ __launch_bounds__(256) void hebb_update_kernel(
    const float* __restrict__ h_pre, const float* __restrict__ hebb,
    float* __restrict__ out_hebb)
{
    const int row0 = blockIdx.x * CROWS;
    const int tid  = threadIdx.x;
#pragma unroll
    for (int r = 0; r < CROWS; ++r) {
        const int bh = row0 + r;
        const int b  = bh >> 10;
        const float hpv = __ldg(&h_pre[bh]);   // h_pre[b*H + h] == h_pre[bh]
        const float4 e = ldcs4(reinterpret_cast<const float4*>(hebb) + bh * (HH / 4) + tid);
        const float4 t = reinterpret_cast<const float4*>(&g_etah[b][0])[tid];
        float4 o;
        o.x = fminf(fmaxf(fmaf(hpv, t.x, e.x), -CLIPV), CLIPV);
        o.y = fminf(fmaxf(fmaf(hpv, t.y, e.y), -CLIPV), CLIPV);
        o.z = fminf(fmaxf(fmaf(hpv, t.z, e.z), -CLIPV), CLIPV);
        o.w = fminf(fmaxf(fmaf(hpv, t.w, e.w), -CLIPV), CLIPV);
        stcs4(reinterpret_cast<float4*>(out_hebb) + bh * (HH / 4) + tid, o);
    }
}

// ---------------------------------------------------------------------------
// Launch. Inputs in metadata order:
// 0 x, 1 h_pre, 2 hebb, 3 fc_w, 4 fc_b, 5 weight, 6 alpha,
// 7 ln_g, 8 ln_b, 9 mod_w, 10 mod_b, 11 modf_w, 12 modf_b
// Output: h_post [64*1024] | m [64] | hebb_new [64*1024*1024], fp32.
// ---------------------------------------------------------------------------
extern "C" void kernel_launch(void* const* d_in, const int* in_sizes, int n_in,
                              void* d_out, int out_size)
{
    const float* x      = (const float*)d_in[0];
    const float* h_pre  = (const float*)d_in[1];
    const float* hebb   = (const float*)d_in[2];
    const float* fc_w   = (const float*)d_in[3];
    const float* fc_b   = (const float*)d_in[4];
    const float* weight = (const float*)d_in[5];
    const float* alpha  = (const float*)d_in[6];
    const float* ln_g   = (const float*)d_in[7];
    const float* ln_b   = (const float*)d_in[8];
    const float* mod_w  = (const float*)d_in[9];
    const float* mod_b  = (const float*)d_in[10];
    const float* modf_w = (const float*)d_in[11];
    const float* modf_b = (const float*)d_in[12];

    float* out       = (float*)d_out;
    float* out_hpost = out;                 // 64*1024
    float* out_m     = out + BB * HH;       // 64
    float* out_hebb  = out + BB * HH + BB;  // 64*1024*1024

    gemm_kernel<<<HH / 16, 256>>>(x, fc_w);
    rec_partial_kernel<<<dim3(NCHUNK, BGROUPS), 256>>>(h_pre, hebb, weight, alpha);
    presum_kernel<<<dim3(BB, 8), 256>>>(fc_b);
    ln_mod_kernel<<<BB, 256>>>(ln_g, ln_b, mod_w, mod_b, modf_w, modf_b,
                               out_hpost, out_m);
    hebb_update_kernel<<<(BB * HH) / CROWS, 256>>>(h_pre, hebb, out_hebb);
}

// round 9
// speedup vs baseline: 1.4199x; 1.0864x over previous
#include <cuda_runtime.h>

#define BB 64
#define II 512
#define HH 1024
#define NCHUNK 32              // h-dimension split for rec partials
#define HCHUNK (HH / NCHUNK)   // 32
#define BTILE 2                // batches per block in rec kernel
#define BGROUPS (BB / BTILE)   // 32
#define CROWS 8                // (b,h) rows per block in hebb update
#define CLIPV 2.0f
#define LN_EPS 1e-5f

// Scratch (no allocations allowed -> __device__ globals)
__device__ float g_rec_part[NCHUNK][BB][HH];   // 8 MB partial sums (.wb -> L2)
__device__ float g_gemm[BB][HH];               // x @ fc_w^T
__device__ float g_pre[BB][HH];                // gemm + fc_b + sum(partials)
__device__ float g_etah[BB][HH];               // eta * h_post

__device__ __forceinline__ float4 ldcs4(const float4* p)
{
    float4 v;
    asm volatile("ld.global.cs.v4.f32 {%0,%1,%2,%3}, [%4];"
                 : "=f"(v.x), "=f"(v.y), "=f"(v.z), "=f"(v.w) : "l"(p));
    return v;
}

__device__ __forceinline__ void stcs4(float4* p, float4 v)
{
    asm volatile("st.global.cs.v4.f32 [%0], {%1,%2,%3,%4};"
                 :: "l"(p), "f"(v.x), "f"(v.y), "f"(v.z), "f"(v.w));
}

// ---------------------------------------------------------------------------
// Kernel A: rec partials.
// part[chunk][b][k] = sum_{h in chunk} h_pre[b,h]*(weight[h,k]+alpha[h,k]*hebb[b,h,k])
// R8 change: BTILE 4->2, grid 512->1024 blocks, __launch_bounds__(256,5)
// -> ~40 resident warps/SM (occupancy is the empirically binding lever:
// 8 warps/SM = 1 TB/s (R3), ~28 = 3.3 TB/s (R5), target ~6 TB/s).
// weight/alpha L2 leg doubles to 256 MB (~23us @ L2 BW), hidden under the
// 268 MB / ~45us DRAM leg.
// ---------------------------------------------------------------------------
__global__ __launch_bounds__(256, 5) void rec_partial_kernel(
    const float* __restrict__ h_pre, const float* __restrict__ hebb,
    const float* __restrict__ weight, const float* __restrict__ alpha)
{
    const int chunk = blockIdx.x;        // 0..NCHUNK-1
    const int bg    = blockIdx.y;        // 0..BGROUPS-1
    const int tid   = threadIdx.x;       // 0..255 -> float4 lane over k
    const int b0    = bg * BTILE;
    const int h0    = chunk * HCHUNK;

    __shared__ float hp[BTILE][HCHUNK];
    if (tid < BTILE * HCHUNK) {
        int j  = tid >> 5;               // 0..1
        int hh = tid & 31;               // 0..31
        hp[j][hh] = h_pre[(b0 + j) * HH + h0 + hh];
    }
    __syncthreads();

    const float4* w4 = reinterpret_cast<const float4*>(weight);
    const float4* a4 = reinterpret_cast<const float4*>(alpha);
    const float4* e4 = reinterpret_cast<const float4*>(hebb);

    float4 acc[BTILE];
#pragma unroll
    for (int j = 0; j < BTILE; ++j) acc[j] = make_float4(0.f, 0.f, 0.f, 0.f);

    const float4* pj[BTILE];
#pragma unroll
    for (int j = 0; j < BTILE; ++j)
        pj[j] = e4 + ((b0 + j) * HH + h0) * (HH / 4) + tid;

#pragma unroll 2
    for (int hi = 0; hi < HCHUNK; ++hi) {
        const int h = h0 + hi;
        const float4 w = w4[h * (HH / 4) + tid];
        const float4 a = a4[h * (HH / 4) + tid];
        float4 e[BTILE];
#pragma unroll
        for (int j = 0; j < BTILE; ++j)
            e[j] = ldcs4(pj[j] + hi * (HH / 4));
#pragma unroll
        for (int j = 0; j < BTILE; ++j) {
            const float s = hp[j][hi];
            acc[j].x += s * fmaf(a.x, e[j].x, w.x);
            acc[j].y += s * fmaf(a.y, e[j].y, w.y);
            acc[j].z += s * fmaf(a.z, e[j].z, w.z);
            acc[j].w += s * fmaf(a.w, e[j].w, w.w);
        }
    }

#pragma unroll
    for (int j = 0; j < BTILE; ++j) {
        float4* dst = reinterpret_cast<float4*>(&g_rec_part[chunk][b0 + j][0]);
        dst[tid] = acc[j];   // .wb: keep in L2 for presum
    }
}

// ---------------------------------------------------------------------------
// Kernel B1: g_gemm[b,k] = sum_i x[b,i] * fc_w[k,i]   (64x1024x512)
// 64 blocks; each block: 64 b x 16 k over full I. (R7-measured OK.)
// ---------------------------------------------------------------------------
__global__ __launch_bounds__(256) void gemm_kernel(
    const float* __restrict__ x, const float* __restrict__ fc_w)
{
    __shared__ float xs[64][33];   // [b][i-chunk]
    __shared__ float ws[16][33];   // [k][i-chunk]
    const int k0  = blockIdx.x * 16;
    const int tid = threadIdx.x;
    const int tx  = tid & 15;   // k within tile
    const int ty  = tid >> 4;   // b group (4 rows)

    float acc[4] = {0.f, 0.f, 0.f, 0.f};

    for (int i0 = 0; i0 < II; i0 += 32) {
        __syncthreads();
#pragma unroll
        for (int r = 0; r < 8; ++r) {
            int idx = tid + r * 256;
            int row = idx >> 5;   // 0..63
            int col = idx & 31;   // 0..31
            xs[row][col] = x[row * II + i0 + col];
        }
        {
            int row = tid >> 5;   // 0..7 -> two passes cover 16 rows
            int col = tid & 31;
            ws[row][col]     = fc_w[(k0 + row) * II + i0 + col];
            ws[row + 8][col] = fc_w[(k0 + row + 8) * II + i0 + col];
        }
        __syncthreads();
#pragma unroll
        for (int ii = 0; ii < 32; ++ii) {
            const float wv = ws[tx][ii];
#pragma unroll
            for (int q = 0; q < 4; ++q)
                acc[q] = fmaf(xs[ty * 4 + q][ii], wv, acc[q]);
        }
    }

#pragma unroll
    for (int q = 0; q < 4; ++q)
        g_gemm[ty * 4 + q][k0 + tx] = acc[q];
}

// ---------------------------------------------------------------------------
// Kernel B1b: presum. g_pre[b,k] = g_gemm[b,k] + fc_b[k] + sum_c part[c][b][k]
// Grid (64 b, 8 k-slices) = 512 blocks; partials L2-hot. (R7-measured OK.)
// ---------------------------------------------------------------------------
__global__ __launch_bounds__(256) void presum_kernel(const float* __restrict__ fc_b)
{
    const int b    = blockIdx.x;
    const int sl   = blockIdx.y;          // k-slice: 128 floats = 32 float4
    const int tid  = threadIdx.x;
    const int lane = tid & 31;            // float4 lane within slice
    const int cg   = tid >> 5;            // chunk group 0..7

    const int f4base = sl * 32 + lane;    // float4 index within row

    float4 s = make_float4(0.f, 0.f, 0.f, 0.f);
#pragma unroll
    for (int c = 0; c < 4; ++c) {
        const float4 p = reinterpret_cast<const float4*>(&g_rec_part[cg * 4 + c][b][0])[f4base];
        s.x += p.x; s.y += p.y; s.z += p.z; s.w += p.w;
    }

    __shared__ float4 red[8][32];
    red[cg][lane] = s;
    __syncthreads();

    if (cg == 0) {
        float4 v = red[0][lane];
#pragma unroll
        for (int g = 1; g < 8; ++g) {
            const float4 p = red[g][lane];
            v.x += p.x; v.y += p.y; v.z += p.z; v.w += p.w;
        }
        const float4 gm = reinterpret_cast<const float4*>(&g_gemm[b][0])[f4base];
        const float4 fb = reinterpret_cast<const float4*>(fc_b)[f4base];
        v.x += gm.x + fb.x; v.y += gm.y + fb.y;
        v.z += gm.z + fb.z; v.w += gm.w + fb.w;
        reinterpret_cast<float4*>(&g_pre[b][0])[f4base] = v;
    }
}

// ---------------------------------------------------------------------------
// Kernel B2: per-batch LN + tanh + m + etah (reads only g_pre, L2-hot).
// ---------------------------------------------------------------------------
__device__ __forceinline__ float block_reduce_sum(float v, float* sred, int tid)
{
#pragma unroll
    for (int o = 16; o > 0; o >>= 1) v += __shfl_down_sync(0xffffffffu, v, o);
    if ((tid & 31) == 0) sred[tid >> 5] = v;
    __syncthreads();
    if (tid < 8) {
        float x = sred[tid];
#pragma unroll
        for (int o = 4; o > 0; o >>= 1) x += __shfl_down_sync(0xffu, x, o);
        if (tid == 0) sred[0] = x;
    }
    __syncthreads();
    float r = sred[0];
    __syncthreads();   // protect sred for next reduction
    return r;
}

__global__ __launch_bounds__(256) void ln_mod_kernel(
    const float* __restrict__ ln_g,  const float* __restrict__ ln_b,
    const float* __restrict__ mod_w, const float* __restrict__ mod_b,
    const float* __restrict__ modf_w, const float* __restrict__ modf_b,
    float* __restrict__ out_hpost, float* __restrict__ out_m)
{
    const int b   = blockIdx.x;
    const int tid = threadIdx.x;
    __shared__ float sred[8];
    __shared__ float sm;

    float4 v = reinterpret_cast<const float4*>(&g_pre[b][0])[tid];

    float s  = v.x + v.y + v.z + v.w;
    float s2 = v.x * v.x + v.y * v.y + v.z * v.z + v.w * v.w;
    s  = block_reduce_sum(s,  sred, tid);
    s2 = block_reduce_sum(s2, sred, tid);
    const float mu   = s / (float)HH;
    const float var  = s2 / (float)HH - mu * mu;
    const float rstd = rsqrtf(var + LN_EPS);

    float4 g  = reinterpret_cast<const float4*>(ln_g)[tid];
    float4 be = reinterpret_cast<const float4*>(ln_b)[tid];
    float4 hp;
    hp.x = tanhf((v.x - mu) * rstd * g.x + be.x);
    hp.y = tanhf((v.y - mu) * rstd * g.y + be.y);
    hp.z = tanhf((v.z - mu) * rstd * g.z + be.z);
    hp.w = tanhf((v.w - mu) * rstd * g.w + be.w);
    reinterpret_cast<float4*>(out_hpost + b * HH)[tid] = hp;

    // m = tanh(dot(h_post, mod_w) + mod_b)
    float4 mw = reinterpret_cast<const float4*>(mod_w)[tid];
    float d = hp.x * mw.x + hp.y * mw.y + hp.z * mw.z + hp.w * mw.w;
    d = block_reduce_sum(d, sred, tid);
    if (tid == 0) {
        float m = tanhf(d + mod_b[0]);
        out_m[b] = m;
        sm = m;
    }
    __syncthreads();
    const float m = sm;

    // etah[b,k] = (m*modf_w[k] + modf_b[k]) * h_post[b,k]
    float4 fw  = reinterpret_cast<const float4*>(modf_w)[tid];
    float4 fbb = reinterpret_cast<const float4*>(modf_b)[tid];
    float4 t;
    t.x = fmaf(m, fw.x, fbb.x) * hp.x;
    t.y = fmaf(m, fw.y, fbb.y) * hp.y;
    t.z = fmaf(m, fw.z, fbb.z) * hp.z;
    t.w = fmaf(m, fw.w, fbb.w) * hp.w;
    reinterpret_cast<float4*>(&g_etah[b][0])[tid] = t;
}

// ---------------------------------------------------------------------------
// Kernel C: hebb_new[b,h,k] = clip(hebb[b,h,k] + h_pre[b,h]*etah[b,k])
// Measured at ~76% of HBM spec in R3/R5/R6/R7 (practical ceiling); unchanged.
// ---------------------------------------------------------------------------
__global__ __launch_bounds__(256) void hebb_update_kernel(
    const float* __restrict__ h_pre, const float* __restrict__ hebb,
    float* __restrict__ out_hebb)
{
    const int row0 = blockIdx.x * CROWS;
    const int tid  = threadIdx.x;
#pragma unroll
    for (int r = 0; r < CROWS; ++r) {
        const int bh = row0 + r;
        const int b  = bh >> 10;
        const float hpv = __ldg(&h_pre[bh]);   // h_pre[b*H + h] == h_pre[bh]
        const float4 e = ldcs4(reinterpret_cast<const float4*>(hebb) + bh * (HH / 4) + tid);
        const float4 t = reinterpret_cast<const float4*>(&g_etah[b][0])[tid];
        float4 o;
        o.x = fminf(fmaxf(fmaf(hpv, t.x, e.x), -CLIPV), CLIPV);
        o.y = fminf(fmaxf(fmaf(hpv, t.y, e.y), -CLIPV), CLIPV);
        o.z = fminf(fmaxf(fmaf(hpv, t.z, e.z), -CLIPV), CLIPV);
        o.w = fminf(fmaxf(fmaf(hpv, t.w, e.w), -CLIPV), CLIPV);
        stcs4(reinterpret_cast<float4*>(out_hebb) + bh * (HH / 4) + tid, o);
    }
}

// ---------------------------------------------------------------------------
// Launch. Inputs in metadata order:
// 0 x, 1 h_pre, 2 hebb, 3 fc_w, 4 fc_b, 5 weight, 6 alpha,
// 7 ln_g, 8 ln_b, 9 mod_w, 10 mod_b, 11 modf_w, 12 modf_b
// Output: h_post [64*1024] | m [64] | hebb_new [64*1024*1024], fp32.
// ---------------------------------------------------------------------------
extern "C" void kernel_launch(void* const* d_in, const int* in_sizes, int n_in,
                              void* d_out, int out_size)
{
    const float* x      = (const float*)d_in[0];
    const float* h_pre  = (const float*)d_in[1];
    const float* hebb   = (const float*)d_in[2];
    const float* fc_w   = (const float*)d_in[3];
    const float* fc_b   = (const float*)d_in[4];
    const float* weight = (const float*)d_in[5];
    const float* alpha  = (const float*)d_in[6];
    const float* ln_g   = (const float*)d_in[7];
    const float* ln_b   = (const float*)d_in[8];
    const float* mod_w  = (const float*)d_in[9];
    const float* mod_b  = (const float*)d_in[10];
    const float* modf_w = (const float*)d_in[11];
    const float* modf_b = (const float*)d_in[12];

    float* out       = (float*)d_out;
    float* out_hpost = out;                 // 64*1024
    float* out_m     = out + BB * HH;       // 64
    float* out_hebb  = out + BB * HH + BB;  // 64*1024*1024

    gemm_kernel<<<HH / 16, 256>>>(x, fc_w);
    rec_partial_kernel<<<dim3(NCHUNK, BGROUPS), 256>>>(h_pre, hebb, weight, alpha);
    presum_kernel<<<dim3(BB, 8), 256>>>(fc_b);
    ln_mod_kernel<<<BB, 256>>>(ln_g, ln_b, mod_w, mod_b, modf_w, modf_b,
                               out_hpost, out_m);
    hebb_update_kernel<<<(BB * HH) / CROWS, 256>>>(h_pre, hebb, out_hebb);
}